// round 2
// baseline (speedup 1.0000x reference)
#include <cuda_runtime.h>
#include <math.h>

#define NB 8
#define NS 512
#define NE 64
#define NH 8
#define NW 8
#define NCHUNK 4
#define ROWS_PC (NS / NCHUNK)   // 128 query rows per block

// scratch: attention context in [B, S, E] layout (E = H*8)
__device__ float g_ctx[NB * NS * NE];

// ---------------------------------------------------------------------------
// Kernel 1: analytic quantum heads + self-attention for one (b, h, chunk).
//   q[s][k]: k>=1 -> prod_{j<=k} cos(x_j+th_j);  k==0 -> prod_{j=1..7} cos(...)
//   scores = q q^T / sqrt(8), softmax over keys, ctx = p @ q
// ---------------------------------------------------------------------------
__global__ __launch_bounds__(256, 2)
void qattn_kernel(const float* __restrict__ x, const float* __restrict__ theta)
{
    __shared__ float qT[NW][NS];   // transposed q: qT[k][t], conflict-free per-k

    const int blk   = blockIdx.x;
    const int chunk = blk & (NCHUNK - 1);
    const int h     = (blk >> 2) & (NH - 1);
    const int b     = blk >> 5;
    const int tid   = threadIdx.x;

    float th[NW];
#pragma unroll
    for (int k = 0; k < NW; k++) th[k] = __ldg(&theta[k]);

    // ---- build q for ALL 512 keys of this head ----
    for (int s = tid; s < NS; s += 256) {
        const float* xp = x + ((b * NS + s) * NE + h * NW);
        float c[NW];
#pragma unroll
        for (int k = 0; k < NW; k++) c[k] = cosf(xp[k] + th[k]);
        float e[NW];
        float run = c[0];
#pragma unroll
        for (int j = 1; j < NW; j++) { run *= c[j]; e[j] = run; }
        float r = c[NW - 1];
#pragma unroll
        for (int j = NW - 2; j >= 1; j--) r *= c[j];
        e[0] = r;
#pragma unroll
        for (int k = 0; k < NW; k++) qT[k][s] = e[k];
    }
    __syncthreads();

    const int warp = tid >> 5, lane = tid & 31;
    const float scale = 0.35355339059327373f;   // 1/sqrt(8)
    const int row_base = chunk * ROWS_PC;

    // each warp handles 2 query rows per pass; keys swept once per pair
    for (int rr = warp * 2; rr < ROWS_PC; rr += 16) {
        const int s0 = row_base + rr, s1 = s0 + 1;
        float q0[NW], q1[NW];
#pragma unroll
        for (int k = 0; k < NW; k++) { q0[k] = qT[k][s0]; q1[k] = qT[k][s1]; }

        float sc0[16], sc1[16];
        float m0 = -1e30f, m1 = -1e30f;
#pragma unroll
        for (int i = 0; i < 16; i++) {
            const int t = lane + 32 * i;
            float kv[NW];
#pragma unroll
            for (int k = 0; k < NW; k++) kv[k] = qT[k][t];
            float d0 = 0.f, d1 = 0.f;
#pragma unroll
            for (int k = 0; k < NW; k++) {
                d0 = fmaf(kv[k], q0[k], d0);
                d1 = fmaf(kv[k], q1[k], d1);
            }
            sc0[i] = d0 * scale; sc1[i] = d1 * scale;
            m0 = fmaxf(m0, sc0[i]); m1 = fmaxf(m1, sc1[i]);
        }
#pragma unroll
        for (int o = 16; o >= 1; o >>= 1) {
            m0 = fmaxf(m0, __shfl_xor_sync(0xffffffffu, m0, o));
            m1 = fmaxf(m1, __shfl_xor_sync(0xffffffffu, m1, o));
        }

        float l0 = 0.f, l1 = 0.f;
        float a0[NW], a1[NW];
#pragma unroll
        for (int k = 0; k < NW; k++) { a0[k] = 0.f; a1[k] = 0.f; }
#pragma unroll
        for (int i = 0; i < 16; i++) {
            const int t = lane + 32 * i;
            const float e0 = __expf(sc0[i] - m0);
            const float e1 = __expf(sc1[i] - m1);
            l0 += e0; l1 += e1;
            float kv[NW];
#pragma unroll
            for (int k = 0; k < NW; k++) kv[k] = qT[k][t];
#pragma unroll
            for (int k = 0; k < NW; k++) {
                a0[k] = fmaf(e0, kv[k], a0[k]);
                a1[k] = fmaf(e1, kv[k], a1[k]);
            }
        }
#pragma unroll
        for (int o = 16; o >= 1; o >>= 1) {
            l0 += __shfl_xor_sync(0xffffffffu, l0, o);
            l1 += __shfl_xor_sync(0xffffffffu, l1, o);
        }
#pragma unroll
        for (int k = 0; k < NW; k++) {
#pragma unroll
            for (int o = 16; o >= 1; o >>= 1) {
                a0[k] += __shfl_xor_sync(0xffffffffu, a0[k], o);
                a1[k] += __shfl_xor_sync(0xffffffffu, a1[k], o);
            }
        }
        if (lane == 0) {
            const float i0 = 1.f / l0, i1 = 1.f / l1;
            float* o0 = g_ctx + ((b * NS + s0) * NE + h * NW);
            float* o1 = g_ctx + ((b * NS + s1) * NE + h * NW);
#pragma unroll
            for (int k = 0; k < NW; k++) { o0[k] = a0[k] * i0; o1[k] = a1[k] * i1; }
        }
    }
}

// ---------------------------------------------------------------------------
// Kernel 2: out[r][o] = sum_e ctx[r][e] * Wo[o][e] + bo[o]   (4096 x 64 x 64)
// ---------------------------------------------------------------------------
__global__ __launch_bounds__(256)
void proj_kernel(const float* __restrict__ Wo, const float* __restrict__ bo,
                 float* __restrict__ out)
{
    __shared__ float WT[NE][NE];       // WT[e][o] = Wo[o*NE + e]
    __shared__ float R[64][NE + 1];    // +1 pad: row-varying banks

    const int tid = threadIdx.x;
    for (int i = tid; i < NE * NE; i += 256) {
        const int o = i >> 6, e = i & 63;
        WT[e][o] = Wo[i];
    }
    const int rowbase = blockIdx.x * 64;
    for (int i = tid; i < 64 * NE; i += 256)
        R[i >> 6][i & 63] = g_ctx[rowbase * NE + i];
    __syncthreads();

    const int tr = tid >> 4, tc = tid & 15;      // 16x16 threads, 4x4 outputs each
    const int r0 = tr * 4, o0 = tc * 4;

    float acc[4][4];
    const float4 bb = *(const float4*)&bo[o0];
#pragma unroll
    for (int i = 0; i < 4; i++) {
        acc[i][0] = bb.x; acc[i][1] = bb.y; acc[i][2] = bb.z; acc[i][3] = bb.w;
    }

#pragma unroll 8
    for (int e = 0; e < NE; e++) {
        const float4 w = *(const float4*)&WT[e][o0];
#pragma unroll
        for (int i = 0; i < 4; i++) {
            const float rv = R[r0 + i][e];
            acc[i][0] = fmaf(rv, w.x, acc[i][0]);
            acc[i][1] = fmaf(rv, w.y, acc[i][1]);
            acc[i][2] = fmaf(rv, w.z, acc[i][2]);
            acc[i][3] = fmaf(rv, w.w, acc[i][3]);
        }
    }
#pragma unroll
    for (int i = 0; i < 4; i++) {
        float4 v = make_float4(acc[i][0], acc[i][1], acc[i][2], acc[i][3]);
        *(float4*)&out[(rowbase + r0 + i) * NE + o0] = v;
    }
}

extern "C" void kernel_launch(void* const* d_in, const int* in_sizes, int n_in,
                              void* d_out, int out_size)
{
    const float* x     = (const float*)d_in[0];
    const float* theta = (const float*)d_in[1];
    const float* Wo    = (const float*)d_in[2];
    const float* bo    = (const float*)d_in[3];
    float* out = (float*)d_out;

    qattn_kernel<<<NB * NH * NCHUNK, 256>>>(x, theta);
    proj_kernel<<<NB * NS / 64, 256>>>(Wo, bo, out);
}

// round 3
// speedup vs baseline: 1.5878x; 1.5878x over previous
#include <cuda_runtime.h>
#include <math.h>

#define NB 8
#define NS 512
#define NE 64
#define NH 8
#define NW 8

// scratch: attention context in [B, S, E] layout (E = H*8)
__device__ float g_ctx[NB * NS * NE];

typedef unsigned long long u64;

__device__ __forceinline__ u64 pk2(float lo, float hi) {
    u64 r; asm("mov.b64 %0,{%1,%2};" : "=l"(r) : "f"(lo), "f"(hi)); return r;
}
__device__ __forceinline__ void unpk2(u64 v, float& lo, float& hi) {
    asm("mov.b64 {%0,%1},%2;" : "=f"(lo), "=f"(hi) : "l"(v));
}
__device__ __forceinline__ void ffma2(u64& d, u64 a, u64 b) {
    asm("fma.rn.f32x2 %0,%1,%2,%0;" : "+l"(d) : "l"(a), "l"(b));
}
__device__ __forceinline__ void fadd2(u64& d, u64 a) {
    asm("add.rn.f32x2 %0,%0,%1;" : "+l"(d) : "l"(a));
}

// ---------------------------------------------------------------------------
// Kernel 1: analytic quantum heads + self-attention.
//   Block = (b, h, half). Thread = one query row. Single key sweep,
//   no max subtraction (|score| <= sqrt(8) so exp is safe), packed f32x2 FMA.
// ---------------------------------------------------------------------------
__global__ __launch_bounds__(256, 1)
void qattn_kernel(const float* __restrict__ x, const float* __restrict__ theta)
{
    __shared__ __align__(16) float q[NS][NW];   // 16 KB, row-major: 32B per token

    const int blk  = blockIdx.x;
    const int half = blk & 1;
    const int h    = (blk >> 1) & (NH - 1);
    const int b    = blk >> 4;
    const int tid  = threadIdx.x;

    float th[NW];
#pragma unroll
    for (int k = 0; k < NW; k++) th[k] = __ldg(&theta[k]);

    // ---- build q for ALL 512 tokens of this head (2 per thread) ----
    // e[j>=1] = prod_{k<=j} cos(x_k+th_k);  e[0] = prod_{k=1..7} cos(x_k+th_k)
    for (int s = tid; s < NS; s += 256) {
        const float* xp = x + ((b * NS + s) * NE + h * NW);
        float c[NW];
#pragma unroll
        for (int k = 0; k < NW; k++) c[k] = cosf(xp[k] + th[k]);
        float e[NW];
        float run = c[0];
#pragma unroll
        for (int j = 1; j < NW; j++) { run *= c[j]; e[j] = run; }
        float r = c[NW - 1];
#pragma unroll
        for (int j = NW - 2; j >= 1; j--) r *= c[j];
        e[0] = r;
        *(float4*)&q[s][0] = make_float4(e[0], e[1], e[2], e[3]);
        *(float4*)&q[s][4] = make_float4(e[4], e[5], e[6], e[7]);
    }
    __syncthreads();

    const int s = half * 256 + tid;               // this thread's query row
    const float scale = 0.35355339059327373f;     // 1/sqrt(8)

    // thread-local scaled query, packed as 4 x f32x2
    u64 qp[4];
    {
        float4 lo4 = *(const float4*)&q[s][0];
        float4 hi4 = *(const float4*)&q[s][4];
        qp[0] = pk2(lo4.x * scale, lo4.y * scale);
        qp[1] = pk2(lo4.z * scale, lo4.w * scale);
        qp[2] = pk2(hi4.x * scale, hi4.y * scale);
        qp[3] = pk2(hi4.z * scale, hi4.w * scale);
    }

    u64 a2[4] = {0ull, 0ull, 0ull, 0ull};   // packed output accumulators
    float l = 0.f;

#pragma unroll 4
    for (int t = 0; t < NS; t++) {
        // key/value row as 4 packed f32x2 (two LDS.128, warp-broadcast)
        ulonglong2 kA = *(const ulonglong2*)&q[t][0];
        ulonglong2 kB = *(const ulonglong2*)&q[t][4];

        // score = q . k (packed, two independent partials)
        u64 d2 = 0ull, d2b = 0ull;
        ffma2(d2,  qp[0], kA.x);
        ffma2(d2b, qp[1], kA.y);
        ffma2(d2,  qp[2], kB.x);
        ffma2(d2b, qp[3], kB.y);
        fadd2(d2, d2b);
        float dl, dh; unpk2(d2, dl, dh);

        const float e = __expf(dl + dh);   // no max needed: |score| <= 2.83
        l += e;
        const u64 ep = pk2(e, e);
        ffma2(a2[0], ep, kA.x);
        ffma2(a2[1], ep, kA.y);
        ffma2(a2[2], ep, kB.x);
        ffma2(a2[3], ep, kB.y);
    }

    const float inv = 1.f / l;
    float o[NW];
#pragma unroll
    for (int i = 0; i < 4; i++) {
        float lo, hi; unpk2(a2[i], lo, hi);
        o[2 * i] = lo * inv; o[2 * i + 1] = hi * inv;
    }
    float* op = g_ctx + ((b * NS + s) * NE + h * NW);
    *(float4*)&op[0] = make_float4(o[0], o[1], o[2], o[3]);
    *(float4*)&op[4] = make_float4(o[4], o[5], o[6], o[7]);
}

// ---------------------------------------------------------------------------
// Kernel 2: out[r][o] = sum_e ctx[r][e] * Wo[o][e] + bo[o]   (4096 x 64 x 64)
// 256 blocks x 16 rows; thread computes 4 outputs of one row.
// ---------------------------------------------------------------------------
__global__ __launch_bounds__(256, 4)
void proj_kernel(const float* __restrict__ Wo, const float* __restrict__ bo,
                 float* __restrict__ out)
{
    __shared__ __align__(16) float WT[NE][NE];   // WT[e][o] = Wo[o*NE + e]
    __shared__ __align__(16) float R[16][NE];

    const int tid = threadIdx.x;
    for (int i = tid; i < NE * NE; i += 256) {
        const int o = i >> 6, e = i & 63;
        WT[e][o] = Wo[i];
    }
    const int rowbase = blockIdx.x * 16;
    for (int i = tid; i < 16 * NE; i += 256)
        R[i >> 6][i & 63] = g_ctx[rowbase * NE + i];
    __syncthreads();

    const int tr = tid >> 4, tc = tid & 15;   // row, 4-col group
    const int o0 = tc * 4;

    float4 acc = *(const float4*)&bo[o0];
#pragma unroll 16
    for (int e = 0; e < NE; e++) {
        const float rv = R[tr][e];
        const float4 w = *(const float4*)&WT[e][o0];
        acc.x = fmaf(rv, w.x, acc.x);
        acc.y = fmaf(rv, w.y, acc.y);
        acc.z = fmaf(rv, w.z, acc.z);
        acc.w = fmaf(rv, w.w, acc.w);
    }
    *(float4*)&out[(rowbase + tr) * NE + o0] = acc;
}

extern "C" void kernel_launch(void* const* d_in, const int* in_sizes, int n_in,
                              void* d_out, int out_size)
{
    const float* x     = (const float*)d_in[0];
    const float* theta = (const float*)d_in[1];
    const float* Wo    = (const float*)d_in[2];
    const float* bo    = (const float*)d_in[3];
    float* out = (float*)d_out;

    qattn_kernel<<<NB * NH * 2, 256>>>(x, theta);
    proj_kernel<<<NB * NS / 16, 256>>>(Wo, bo, out);
}